// round 10
// baseline (speedup 1.0000x reference)
#include <cuda_runtime.h>

// Shapes fixed by reference setup_inputs(): B=4, N=M=8192, D=3.
#define B_      4
#define NPTS    8192
#define SETS    8                   // (cloud 0|1) * 4 batches; set = cloud*4 + b
#define TOTPTS  (SETS * NPTS)       // 65536

// Spatial grid: 64^3 cells over [-8, 8]^3  (h = 0.25)
#define GRIDN   64
#define GLO     (-8.0f)
#define H       0.25f
#define INVH    4.0f
#define C       (GRIDN * GRIDN * GRIDN)     // 262144 cells per set
#define CELLS_TOTAL (SETS * C)              // 2097152
#define SCAN_TPB    1024
#define SCAN_BLOCKS (CELLS_TOTAL / SCAN_TPB) // 2048

// Static scratch (no cudaMalloc allowed).
__device__ int    g_counts[CELLS_TOTAL];        // histogram, then scatter cursor
__device__ int    g_start[CELLS_TOTAL + 1];     // exclusive prefix + sentinel
__device__ int    g_bsum[SCAN_BLOCKS];          // scan block sums
__device__ float4 g_sp[TOTPTS];                 // cell-sorted points (x,y,z, idx-bits)
__device__ float  g_od[TOTPTS];                 // per-point chamfer term (orig-idx slot)
__device__ float  g_on[TOTPTS];                 // per-point normal term  (orig-idx slot)
__device__ float  g_bs_d[256];
__device__ float  g_bs_n[256];

__device__ __forceinline__ int cellcoord(float v) {
    int c = (int)floorf((v - GLO) * INVH);
    return min(max(c, 0), GRIDN - 1);
}

// ---------------------------------------------------------------------------
// Binning pipeline
// ---------------------------------------------------------------------------
__global__ void zero_counts_kernel() {
    g_counts[blockIdx.x * SCAN_TPB + threadIdx.x] = 0;
}

__global__ void hist_kernel(const float* __restrict__ x1,
                            const float* __restrict__ x2)
{
    const int gid = blockIdx.x * 256 + threadIdx.x;     // 0..TOTPTS-1
    const int s = gid >> 13;                            // set
    const int t = gid & (NPTS - 1);
    const float* p = (s >= 4 ? x2 : x1) + ((size_t)(s & 3) * NPTS + t) * 3;
    const int cx = cellcoord(p[0]), cy = cellcoord(p[1]), cz = cellcoord(p[2]);
    atomicAdd(&g_counts[s * C + (cz * GRIDN + cy) * GRIDN + cx], 1);
}

// exclusive scan, stage A: per-block (1024) scan + block sums
__global__ void scanA_kernel() {
    __shared__ int sh[SCAN_TPB];
    const int tid = threadIdx.x;
    const int gid = blockIdx.x * SCAN_TPB + tid;
    const int v = g_counts[gid];
    sh[tid] = v;
    __syncthreads();
#pragma unroll
    for (int off = 1; off < SCAN_TPB; off <<= 1) {
        int t = (tid >= off) ? sh[tid - off] : 0;
        __syncthreads();
        sh[tid] += t;
        __syncthreads();
    }
    g_start[gid] = sh[tid] - v;                 // exclusive within block
    if (tid == SCAN_TPB - 1) g_bsum[blockIdx.x] = sh[tid];
}

// stage B: scan the 2048 block sums (1 block, 1024 threads, 2 elems each)
__global__ void scanB_kernel() {
    __shared__ int sh[SCAN_TPB];
    const int tid = threadIdx.x;
    const int a = g_bsum[2 * tid];
    const int b = g_bsum[2 * tid + 1];
    const int ps = a + b;
    sh[tid] = ps;
    __syncthreads();
#pragma unroll
    for (int off = 1; off < SCAN_TPB; off <<= 1) {
        int t = (tid >= off) ? sh[tid - off] : 0;
        __syncthreads();
        sh[tid] += t;
        __syncthreads();
    }
    const int exc = sh[tid] - ps;               // exclusive over pairs
    g_bsum[2 * tid]     = exc;
    g_bsum[2 * tid + 1] = exc + a;
}

// stage C: add block offsets + write sentinel
__global__ void scanC_kernel() {
    const int gid = blockIdx.x * SCAN_TPB + threadIdx.x;
    g_start[gid] += g_bsum[blockIdx.x];
    if (gid == 0) g_start[CELLS_TOTAL] = TOTPTS;
}

__global__ void scatter_kernel(const float* __restrict__ x1,
                               const float* __restrict__ x2)
{
    const int gid = blockIdx.x * 256 + threadIdx.x;
    const int s = gid >> 13;
    const int t = gid & (NPTS - 1);
    const float* p = (s >= 4 ? x2 : x1) + ((size_t)(s & 3) * NPTS + t) * 3;
    const float vx = p[0], vy = p[1], vz = p[2];
    const int cx = cellcoord(vx), cy = cellcoord(vy), cz = cellcoord(vz);
    const int cid = s * C + (cz * GRIDN + cy) * GRIDN + cx;
    const int pos = g_start[cid] + atomicAdd(&g_counts[cid], 1);
    g_sp[pos] = make_float4(vx, vy, vz, __int_as_float(t));
}

// ---------------------------------------------------------------------------
// NN search: one thread per (sorted) query point; expanding cubic shells with
// exact box-distance termination. Cells consecutive in x map to contiguous
// ranges of g_sp, so each ring row is 1-2 [begin,end) scans.
// Tie-break (d, orig_idx) lexicographic -> result independent of bin order.
// ---------------------------------------------------------------------------
__global__ __launch_bounds__(256)
void nn_search_kernel(const float* __restrict__ n1,
                      const float* __restrict__ n2)
{
    const int gid = blockIdx.x * 256 + threadIdx.x;     // 0..TOTPTS-1
    const int s = gid >> 13;                            // query set
    const int t = gid & (NPTS - 1);                     // sorted position
    const int g = s ^ 4;                                // target set (other cloud)
    const int b = s & 3;

    const float4 q = g_sp[s * NPTS + t];
    const int qorig = __float_as_int(q.w);
    const int cx = cellcoord(q.x), cy = cellcoord(q.y), cz = cellcoord(q.z);

    float bestd = 3.4e38f;
    int   bidx  = 0x7FFFFFFF;
    const int gC = g * C;

    auto scan_range = [&](int cidFirst, int nCells) {
        const int jb = g_start[gC + cidFirst];
        const int je = g_start[gC + cidFirst + nCells];
        for (int j = jb; j < je; j++) {
            const float4 p = g_sp[j];
            const float dx = q.x - p.x, dy = q.y - p.y, dz = q.z - p.z;
            const float d = dx * dx + dy * dy + dz * dz;
            const int oid = __float_as_int(p.w);
            if (d < bestd || (d == bestd && oid < bidx)) { bestd = d; bidx = oid; }
        }
    };

    for (int r = 0; r <= GRIDN; r++) {
        if (r > 0) {
            // searched box = cells [c-(r-1), c+(r-1)] (clamped). Min distance
            // from q to any UNSEARCHED cell; faces at the grid edge excluded
            // (outliers clamp into edge cells, which get scanned exactly).
            float bnd = 1e30f;
            int e;
            e = cx - (r - 1); if (e > 0)          bnd = fminf(bnd, q.x - (GLO + e * H));
            e = cx + (r - 1); if (e < GRIDN - 1)  bnd = fminf(bnd, (GLO + (e + 1) * H) - q.x);
            e = cy - (r - 1); if (e > 0)          bnd = fminf(bnd, q.y - (GLO + e * H));
            e = cy + (r - 1); if (e < GRIDN - 1)  bnd = fminf(bnd, (GLO + (e + 1) * H) - q.y);
            e = cz - (r - 1); if (e > 0)          bnd = fminf(bnd, q.z - (GLO + e * H));
            e = cz + (r - 1); if (e < GRIDN - 1)  bnd = fminf(bnd, (GLO + (e + 1) * H) - q.z);
            bnd = fmaxf(bnd, 0.0f);
            if (bestd < bnd * bnd) break;
        }
        const int z0 = max(cz - r, 0), z1 = min(cz + r, GRIDN - 1);
        const int y0 = max(cy - r, 0), y1 = min(cy + r, GRIDN - 1);
        const int x0 = max(cx - r, 0), x1 = min(cx + r, GRIDN - 1);
        for (int z = z0; z <= z1; z++) {
            const bool zr = (z == cz - r) || (z == cz + r);
            for (int y = y0; y <= y1; y++) {
                const bool yr = (y == cy - r) || (y == cy + r);
                const int rowbase = (z * GRIDN + y) * GRIDN;
                if (zr || yr) {
                    scan_range(rowbase + x0, x1 - x0 + 1);   // full ring row
                } else {
                    const int xl = cx - r, xr = cx + r;      // ring edges only
                    if (xl >= 0)        scan_range(rowbase + xl, 1);
                    if (xr <= GRIDN - 1) scan_range(rowbase + xr, 1);
                }
            }
        }
    }

    // normal consistency term for the winner
    const float* qn = (s >= 4 ? n2 : n1) + ((size_t)b * NPTS + qorig) * 3;
    const float* tn = (s >= 4 ? n1 : n2) + ((size_t)b * NPTS + bidx) * 3;
    const float dotp = qn[0] * tn[0] + qn[1] * tn[1] + qn[2] * tn[2];
    float na = sqrtf(qn[0] * qn[0] + qn[1] * qn[1] + qn[2] * qn[2]);
    float nb = sqrtf(tn[0] * tn[0] + tn[1] * tn[1] + tn[2] * tn[2]);
    na = fmaxf(na, 1e-6f);
    nb = fmaxf(nb, 1e-6f);

    const int slot = s * NPTS + qorig;          // orig-idx slot: deterministic
    g_od[slot] = bestd;
    g_on[slot] = 1.0f - fabsf(dotp / (na * nb));
}

// ---------------------------------------------------------------------------
// Deterministic reductions
// ---------------------------------------------------------------------------
__global__ __launch_bounds__(256)
void reduce_kernel()
{
    __shared__ float sd[256];
    __shared__ float sn[256];
    const int tid = threadIdx.x;
    const int i = blockIdx.x * 256 + tid;
    sd[tid] = g_od[i];
    sn[tid] = g_on[i];
    __syncthreads();
#pragma unroll
    for (int o = 128; o > 0; o >>= 1) {
        if (tid < o) { sd[tid] += sd[tid + o]; sn[tid] += sn[tid + o]; }
        __syncthreads();
    }
    if (tid == 0) { g_bs_d[blockIdx.x] = sd[0]; g_bs_n[blockIdx.x] = sn[0]; }
}

__global__ __launch_bounds__(256)
void final_kernel(float* __restrict__ out)
{
    __shared__ float sd[256];
    __shared__ float sn[256];
    const int tid = threadIdx.x;
    sd[tid] = g_bs_d[tid];
    sn[tid] = g_bs_n[tid];
    __syncthreads();
#pragma unroll
    for (int o = 128; o > 0; o >>= 1) {
        if (tid < o) { sd[tid] += sd[tid + o]; sn[tid] += sn[tid + o]; }
        __syncthreads();
    }
    if (tid == 0) {
        const float inv = 1.0f / (float)(B_ * NPTS);
        out[0] = sd[0] * inv;
        out[1] = sn[0] * inv;
    }
}

extern "C" void kernel_launch(void* const* d_in, const int* in_sizes, int n_in,
                              void* d_out, int out_size)
{
    const float* xyz1  = (const float*)d_in[0];
    const float* xyz2  = (const float*)d_in[1];
    const float* nxyz1 = (const float*)d_in[2];
    const float* nxyz2 = (const float*)d_in[3];
    float* out = (float*)d_out;

    zero_counts_kernel<<<SCAN_BLOCKS, SCAN_TPB>>>();
    hist_kernel<<<TOTPTS / 256, 256>>>(xyz1, xyz2);
    scanA_kernel<<<SCAN_BLOCKS, SCAN_TPB>>>();
    scanB_kernel<<<1, SCAN_TPB>>>();
    scanC_kernel<<<SCAN_BLOCKS, SCAN_TPB>>>();
    zero_counts_kernel<<<SCAN_BLOCKS, SCAN_TPB>>>();
    scatter_kernel<<<TOTPTS / 256, 256>>>(xyz1, xyz2);
    nn_search_kernel<<<TOTPTS / 256, 256>>>(nxyz1, nxyz2);
    reduce_kernel<<<TOTPTS / 256, 256>>>();     // 256 blocks (bug fixed: was 1)
    final_kernel<<<1, 256>>>(out);
}

// round 11
// speedup vs baseline: 2.1713x; 2.1713x over previous
#include <cuda_runtime.h>

// Shapes fixed by reference setup_inputs(): B=4, N=M=8192, D=3.
#define B_      4
#define NPTS    8192
#define SETS    8                   // (cloud 0|1) * 4 batches; set = cloud*4 + b
#define TOTPTS  (SETS * NPTS)       // 65536

// Spatial grid: 32^3 cells over [-4, 4]^3  (h = 0.25). N(0,1) coords beyond
// +-4 (~1e-4 of points) clamp into edge cells; the termination bound excludes
// grid-edge faces so clamped points are handled exactly.
#define GRIDN   32
#define GLO     (-4.0f)
#define H       0.25f
#define INVH    4.0f
#define C       (GRIDN * GRIDN * GRIDN)     // 32768 cells per set
#define CELLS_TOTAL (SETS * C)              // 262144
#define SCAN_TPB    1024
#define SCAN_BLOCKS (CELLS_TOTAL / SCAN_TPB) // 256

// Static scratch (no cudaMalloc allowed).
__device__ int    g_counts[CELLS_TOTAL];        // histogram, then scatter cursor
__device__ int    g_start[CELLS_TOTAL + 1];     // exclusive prefix + sentinel
__device__ int    g_bsum[SCAN_BLOCKS];          // scan block sums
__device__ float4 g_sp[TOTPTS];                 // cell-sorted points (x,y,z, idx-bits)
__device__ float  g_od[TOTPTS];                 // per-point chamfer term (orig-idx slot)
__device__ float  g_on[TOTPTS];                 // per-point normal term  (orig-idx slot)
__device__ float  g_bs_d[256];
__device__ float  g_bs_n[256];

__device__ __forceinline__ int cellcoord(float v) {
    int c = (int)floorf((v - GLO) * INVH);
    return min(max(c, 0), GRIDN - 1);
}

// ---------------------------------------------------------------------------
// Binning pipeline
// ---------------------------------------------------------------------------
__global__ void zero_counts_kernel() {
    g_counts[blockIdx.x * SCAN_TPB + threadIdx.x] = 0;
}

__global__ void hist_kernel(const float* __restrict__ x1,
                            const float* __restrict__ x2)
{
    const int gid = blockIdx.x * 256 + threadIdx.x;     // 0..TOTPTS-1
    const int s = gid >> 13;                            // set
    const int t = gid & (NPTS - 1);
    const float* p = (s >= 4 ? x2 : x1) + ((size_t)(s & 3) * NPTS + t) * 3;
    const int cx = cellcoord(p[0]), cy = cellcoord(p[1]), cz = cellcoord(p[2]);
    atomicAdd(&g_counts[s * C + (cz * GRIDN + cy) * GRIDN + cx], 1);
}

// stage A: per-block (1024) exclusive scan + block sums; also zeroes g_counts
// so the scatter cursor is ready without a second zeroing launch.
__global__ void scanA_kernel() {
    __shared__ int sh[SCAN_TPB];
    const int tid = threadIdx.x;
    const int gid = blockIdx.x * SCAN_TPB + tid;
    const int v = g_counts[gid];
    g_counts[gid] = 0;                          // reset cursor for scatter
    sh[tid] = v;
    __syncthreads();
#pragma unroll
    for (int off = 1; off < SCAN_TPB; off <<= 1) {
        int t = (tid >= off) ? sh[tid - off] : 0;
        __syncthreads();
        sh[tid] += t;
        __syncthreads();
    }
    g_start[gid] = sh[tid] - v;                 // exclusive within block
    if (tid == SCAN_TPB - 1) g_bsum[blockIdx.x] = sh[tid];
}

// stage B: exclusive scan of the 256 block sums (1 block, 256 threads)
__global__ void scanB_kernel() {
    __shared__ int sh[SCAN_BLOCKS];
    const int tid = threadIdx.x;
    const int v = g_bsum[tid];
    sh[tid] = v;
    __syncthreads();
#pragma unroll
    for (int off = 1; off < SCAN_BLOCKS; off <<= 1) {
        int t = (tid >= off) ? sh[tid - off] : 0;
        __syncthreads();
        sh[tid] += t;
        __syncthreads();
    }
    g_bsum[tid] = sh[tid] - v;                  // exclusive
}

// stage C: add block offsets + sentinel
__global__ void scanC_kernel() {
    const int gid = blockIdx.x * SCAN_TPB + threadIdx.x;
    g_start[gid] += g_bsum[blockIdx.x];
    if (gid == 0) g_start[CELLS_TOTAL] = TOTPTS;
}

__global__ void scatter_kernel(const float* __restrict__ x1,
                               const float* __restrict__ x2)
{
    const int gid = blockIdx.x * 256 + threadIdx.x;
    const int s = gid >> 13;
    const int t = gid & (NPTS - 1);
    const float* p = (s >= 4 ? x2 : x1) + ((size_t)(s & 3) * NPTS + t) * 3;
    const float vx = p[0], vy = p[1], vz = p[2];
    const int cx = cellcoord(vx), cy = cellcoord(vy), cz = cellcoord(vz);
    const int cid = s * C + (cz * GRIDN + cy) * GRIDN + cx;
    const int pos = g_start[cid] + atomicAdd(&g_counts[cid], 1);
    g_sp[pos] = make_float4(vx, vy, vz, __int_as_float(t));
}

// ---------------------------------------------------------------------------
// NN search. Phase 1: 3x3x3 box with ALL row ranges prefetched (<=18
// independent g_start loads -> one exposed latency), then candidate stream.
// Phase 2 (rare): expanding rings r>=2 with exact box-distance termination.
// Tie-break (d, orig_idx) lexicographic -> independent of bin order.
// ---------------------------------------------------------------------------
__global__ __launch_bounds__(128)
void nn_search_kernel(const float* __restrict__ n1,
                      const float* __restrict__ n2)
{
    const int gid = blockIdx.x * 128 + threadIdx.x;     // 0..TOTPTS-1
    const int s = gid >> 13;                            // query set
    const int t = gid & (NPTS - 1);                     // sorted position
    const int g = s ^ 4;                                // target set (other cloud)
    const int b = s & 3;

    const float4 q = g_sp[s * NPTS + t];
    const int qorig = __float_as_int(q.w);
    const int cx = cellcoord(q.x), cy = cellcoord(q.y), cz = cellcoord(q.z);

    float bestd = 3.4e38f;
    int   bidx  = 0x7FFFFFFF;
    const int gC = g * C;

    // ---- phase 1: 3^3 box, prefetched ranges (clamp duplicates are harmless:
    // scanning the same candidates twice cannot change a min) ----
    {
        const int x0 = max(cx - 1, 0), x1 = min(cx + 1, GRIDN - 1);
        const int nx = x1 - x0 + 1;
        int jbs[9], jes[9];
#pragma unroll
        for (int dz = -1; dz <= 1; dz++) {
#pragma unroll
            for (int dy = -1; dy <= 1; dy++) {
                const int z = min(max(cz + dz, 0), GRIDN - 1);
                const int y = min(max(cy + dy, 0), GRIDN - 1);
                const int cid = gC + (z * GRIDN + y) * GRIDN + x0;
                const int i = (dz + 1) * 3 + (dy + 1);
                jbs[i] = g_start[cid];
                jes[i] = g_start[cid + nx];
            }
        }
#pragma unroll
        for (int i = 0; i < 9; i++) {
            for (int j = jbs[i]; j < jes[i]; j++) {
                const float4 p = g_sp[j];
                const float dx = q.x - p.x, dy = q.y - p.y, dz = q.z - p.z;
                const float d = dx * dx + dy * dy + dz * dz;
                const int oid = __float_as_int(p.w);
                if (d < bestd || (d == bestd && oid < bidx)) { bestd = d; bidx = oid; }
            }
        }
    }

    // ---- phase 2: rings r >= 2 with exact termination bound ----
    for (int r = 2; r <= GRIDN; r++) {
        // searched box = [c-(r-1), c+(r-1)] clamped; min distance from q to
        // any unsearched cell. Grid-edge faces excluded (clamped outliers
        // live in edge cells, which are scanned exactly).
        float bnd = 1e30f;
        int e;
        e = cx - (r - 1); if (e > 0)          bnd = fminf(bnd, q.x - (GLO + e * H));
        e = cx + (r - 1); if (e < GRIDN - 1)  bnd = fminf(bnd, (GLO + (e + 1) * H) - q.x);
        e = cy - (r - 1); if (e > 0)          bnd = fminf(bnd, q.y - (GLO + e * H));
        e = cy + (r - 1); if (e < GRIDN - 1)  bnd = fminf(bnd, (GLO + (e + 1) * H) - q.y);
        e = cz - (r - 1); if (e > 0)          bnd = fminf(bnd, q.z - (GLO + e * H));
        e = cz + (r - 1); if (e < GRIDN - 1)  bnd = fminf(bnd, (GLO + (e + 1) * H) - q.z);
        bnd = fmaxf(bnd, 0.0f);
        if (bestd < bnd * bnd) break;

        const int z0 = max(cz - r, 0), z1 = min(cz + r, GRIDN - 1);
        const int y0 = max(cy - r, 0), y1 = min(cy + r, GRIDN - 1);
        const int x0 = max(cx - r, 0), x1 = min(cx + r, GRIDN - 1);
        for (int z = z0; z <= z1; z++) {
            const bool zr = (z == cz - r) || (z == cz + r);
            for (int y = y0; y <= y1; y++) {
                const bool yr = (y == cy - r) || (y == cy + r);
                const int rowbase = gC + (z * GRIDN + y) * GRIDN;
                int jb, je;
                if (zr || yr) {
                    jb = g_start[rowbase + x0];
                    je = g_start[rowbase + x1 + 1];
                } else {
                    const int xl = cx - r, xr = cx + r;
                    // scan the two edge cells; fetch both ranges up front
                    int jb2 = 0, je2 = 0;
                    if (xl >= 0)         { jb  = g_start[rowbase + xl]; je  = g_start[rowbase + xl + 1]; }
                    else                 { jb  = 0; je = 0; }
                    if (xr <= GRIDN - 1) { jb2 = g_start[rowbase + xr]; je2 = g_start[rowbase + xr + 1]; }
                    for (int j = jb2; j < je2; j++) {
                        const float4 p = g_sp[j];
                        const float dx = q.x - p.x, dy = q.y - p.y, dz = q.z - p.z;
                        const float d = dx * dx + dy * dy + dz * dz;
                        const int oid = __float_as_int(p.w);
                        if (d < bestd || (d == bestd && oid < bidx)) { bestd = d; bidx = oid; }
                    }
                }
                for (int j = jb; j < je; j++) {
                    const float4 p = g_sp[j];
                    const float dx = q.x - p.x, dy = q.y - p.y, dz = q.z - p.z;
                    const float d = dx * dx + dy * dy + dz * dz;
                    const int oid = __float_as_int(p.w);
                    if (d < bestd || (d == bestd && oid < bidx)) { bestd = d; bidx = oid; }
                }
            }
        }
    }

    // normal consistency term for the winner
    const float* qn = (s >= 4 ? n2 : n1) + ((size_t)b * NPTS + qorig) * 3;
    const float* tn = (s >= 4 ? n1 : n2) + ((size_t)b * NPTS + bidx) * 3;
    const float dotp = qn[0] * tn[0] + qn[1] * tn[1] + qn[2] * tn[2];
    float na = sqrtf(qn[0] * qn[0] + qn[1] * qn[1] + qn[2] * qn[2]);
    float nb = sqrtf(tn[0] * tn[0] + tn[1] * tn[1] + tn[2] * tn[2]);
    na = fmaxf(na, 1e-6f);
    nb = fmaxf(nb, 1e-6f);

    const int slot = s * NPTS + qorig;          // orig-idx slot: deterministic
    g_od[slot] = bestd;
    g_on[slot] = 1.0f - fabsf(dotp / (na * nb));
}

// ---------------------------------------------------------------------------
// Deterministic reductions
// ---------------------------------------------------------------------------
__global__ __launch_bounds__(256)
void reduce_kernel()
{
    __shared__ float sd[256];
    __shared__ float sn[256];
    const int tid = threadIdx.x;
    const int i = blockIdx.x * 256 + tid;
    sd[tid] = g_od[i];
    sn[tid] = g_on[i];
    __syncthreads();
#pragma unroll
    for (int o = 128; o > 0; o >>= 1) {
        if (tid < o) { sd[tid] += sd[tid + o]; sn[tid] += sn[tid + o]; }
        __syncthreads();
    }
    if (tid == 0) { g_bs_d[blockIdx.x] = sd[0]; g_bs_n[blockIdx.x] = sn[0]; }
}

__global__ __launch_bounds__(256)
void final_kernel(float* __restrict__ out)
{
    __shared__ float sd[256];
    __shared__ float sn[256];
    const int tid = threadIdx.x;
    sd[tid] = g_bs_d[tid];
    sn[tid] = g_bs_n[tid];
    __syncthreads();
#pragma unroll
    for (int o = 128; o > 0; o >>= 1) {
        if (tid < o) { sd[tid] += sd[tid + o]; sn[tid] += sn[tid + o]; }
        __syncthreads();
    }
    if (tid == 0) {
        const float inv = 1.0f / (float)(B_ * NPTS);
        out[0] = sd[0] * inv;
        out[1] = sn[0] * inv;
    }
}

extern "C" void kernel_launch(void* const* d_in, const int* in_sizes, int n_in,
                              void* d_out, int out_size)
{
    const float* xyz1  = (const float*)d_in[0];
    const float* xyz2  = (const float*)d_in[1];
    const float* nxyz1 = (const float*)d_in[2];
    const float* nxyz2 = (const float*)d_in[3];
    float* out = (float*)d_out;

    zero_counts_kernel<<<SCAN_BLOCKS, SCAN_TPB>>>();
    hist_kernel<<<TOTPTS / 256, 256>>>(xyz1, xyz2);
    scanA_kernel<<<SCAN_BLOCKS, SCAN_TPB>>>();       // also zeroes counts
    scanB_kernel<<<1, SCAN_BLOCKS>>>();
    scanC_kernel<<<SCAN_BLOCKS, SCAN_TPB>>>();
    scatter_kernel<<<TOTPTS / 256, 256>>>(xyz1, xyz2);
    nn_search_kernel<<<TOTPTS / 128, 128>>>(nxyz1, nxyz2);
    reduce_kernel<<<TOTPTS / 256, 256>>>();
    final_kernel<<<1, 256>>>(out);
}